// round 8
// baseline (speedup 1.0000x reference)
#include <cuda_runtime.h>
#include <cstdint>
#include <cstddef>

// ============================================================================
// RNNLayers: 2-layer LSTM (Keras, activation=selu), B=64, T=2048, F=64, H=128.
//   1) GEMM1: xz = x  @ W1 + b1   -> g_xz   [131072 x 512]
//   2) scan1 (cluster-2): LSTM    -> g_h1
//   3) GEMM2: xz = h1 @ W2 + b2   -> g_xz
//   4) scan2 (cluster-2): LSTM    -> d_out
//
// Scan: each batch row is split across a 2-CTA cluster. CTA rank r owns
// gate-columns ucol = gate*128 + j, j in [r*64, r*64+64). 512 threads:
// bit0 = k-half, bits1-2 = gate, bits3-8 = jj. U is FULLY register-resident
// (64 floats = 32 f32x2 per thread). h (128 floats) is replicated in each
// CTA's smem; per step each CTA writes its 64 new h values locally and to the
// peer via st.shared::cluster, synchronized with full/empty mbarriers.
// ============================================================================

typedef unsigned long long ull;

#define BATCH 64
#define TSEQ  2048
#define FIN   64
#define HID   128

#define SELU_LAM 1.0507009873554804934193349852946f
#define SELU_ALF 1.6732632423543772848170429916717f

__device__ float g_xz[(size_t)BATCH * TSEQ * 4 * HID];  // 256 MB scratch
__device__ float g_h1[(size_t)BATCH * TSEQ * HID];      //  64 MB scratch

__device__ __forceinline__ void fma2(ull& d, ull a, ull b) {
    asm("fma.rn.f32x2 %0, %1, %2, %0;" : "+l"(d) : "l"(a), "l"(b));
}
__device__ __forceinline__ ull pack2(float lo, float hi) {
    ull r; asm("mov.b64 %0, {%1, %2};" : "=l"(r) : "f"(lo), "f"(hi)); return r;
}
__device__ __forceinline__ float2 unpack2(ull v) {
    float2 r; asm("mov.b64 {%0, %1}, %2;" : "=f"(r.x), "=f"(r.y) : "l"(v)); return r;
}
__device__ __forceinline__ ull d2u(double d) { return (ull)__double_as_longlong(d); }

__device__ __forceinline__ uint32_t smem_u32(const void* p) {
    return (uint32_t)__cvta_generic_to_shared(p);
}
__device__ __forceinline__ uint32_t mapa_u32(uint32_t addr, uint32_t rank) {
    uint32_t r; asm("mapa.shared::cluster.u32 %0, %1, %2;" : "=r"(r) : "r"(addr), "r"(rank));
    return r;
}
__device__ __forceinline__ void st_remote_f32(uint32_t raddr, float v) {
    asm volatile("st.shared::cluster.f32 [%0], %1;" :: "r"(raddr), "f"(v) : "memory");
}
__device__ __forceinline__ void mbar_init(uint32_t a, uint32_t cnt) {
    asm volatile("mbarrier.init.shared.b64 [%0], %1;" :: "r"(a), "r"(cnt) : "memory");
}
__device__ __forceinline__ void mbar_arrive_local(uint32_t a) {
    asm volatile("mbarrier.arrive.shared.b64 _, [%0];" :: "r"(a) : "memory");
}
__device__ __forceinline__ void mbar_arrive_remote(uint32_t raddr) {
    asm volatile("mbarrier.arrive.release.cluster.shared::cluster.b64 _, [%0];"
                 :: "r"(raddr) : "memory");
}
#define MBAR_WAIT(addr, par) do {                                              \
    uint32_t _done;                                                            \
    asm volatile("{\n\t.reg .pred p;\n\t"                                      \
        "mbarrier.try_wait.parity.acquire.cluster.shared::cta.b64 p, [%1], %2;\n\t" \
        "selp.b32 %0, 1, 0, p;\n\t}"                                           \
        : "=r"(_done) : "r"(addr), "r"(par) : "memory");                       \
    while (!_done) {                                                           \
        asm volatile("{\n\t.reg .pred p;\n\t"                                  \
            "mbarrier.try_wait.parity.acquire.cluster.shared::cta.b64 p, [%1], %2, 0x989680;\n\t" \
            "selp.b32 %0, 1, 0, p;\n\t}"                                       \
            : "=r"(_done) : "r"(addr), "r"(par) : "memory");                   \
    }                                                                          \
} while (0)
#define CLUSTER_SYNC_() do {                                                   \
    asm volatile("barrier.cluster.arrive.aligned;" ::: "memory");              \
    asm volatile("barrier.cluster.wait.aligned;" ::: "memory");                \
} while (0)

// ============================================================================
// GEMM: Y[M,512] = X[M,K] @ W[K,512] + bias.  BM=128, BN=128, K loaded whole.
// ============================================================================
template<int K>
__global__ __launch_bounds__(256, 1)
void gemm_xz(const float* __restrict__ X, const float* __restrict__ W,
             const float* __restrict__ bias, float* __restrict__ Y) {
    extern __shared__ float sm[];
    float* s_a = sm;                     // [128][K+1]
    float* s_b = sm + 128 * (K + 1);     // [K][128]
    const int tid = threadIdx.x;
    const int bm  = blockIdx.x * 128;
    const int bn  = blockIdx.y * 128;

    #pragma unroll 8
    for (int i = tid; i < 128 * K; i += 256) {
        int m = i / K, k = i - m * K;
        s_a[m * (K + 1) + k] = X[(size_t)(bm + m) * K + k];
    }
    #pragma unroll 4
    for (int i = tid * 4; i < K * 128; i += 1024) {
        int k = i >> 7, n = i & 127;
        *(float4*)(s_b + k * 128 + n) = *(const float4*)(W + (size_t)k * 512 + bn + n);
    }
    __syncthreads();

    const int tmi = tid & 15;
    const int tn  = (tid >> 4) << 3;
    ull acc[8][4] = {};
    const float* sbp = s_b + tn;

    #pragma unroll 4
    for (int k = 0; k < K; ++k) {
        float4 b0 = *(const float4*)(sbp + k * 128);
        float4 b1 = *(const float4*)(sbp + k * 128 + 4);
        ull bb0 = pack2(b0.x, b0.y), bb1 = pack2(b0.z, b0.w);
        ull bb2 = pack2(b1.x, b1.y), bb3 = pack2(b1.z, b1.w);
        #pragma unroll
        for (int r = 0; r < 8; ++r) {
            float a = s_a[(tmi + (r << 4)) * (K + 1) + k];
            ull aa = pack2(a, a);
            fma2(acc[r][0], aa, bb0);
            fma2(acc[r][1], aa, bb1);
            fma2(acc[r][2], aa, bb2);
            fma2(acc[r][3], aa, bb3);
        }
    }

    float4 bv0 = *(const float4*)(bias + bn + tn);
    float4 bv1 = *(const float4*)(bias + bn + tn + 4);
    #pragma unroll
    for (int r = 0; r < 8; ++r) {
        int row = bm + tmi + (r << 4);
        float2 c0 = unpack2(acc[r][0]);
        float2 c1 = unpack2(acc[r][1]);
        float2 c2 = unpack2(acc[r][2]);
        float2 c3 = unpack2(acc[r][3]);
        float4 o0 = make_float4(c0.x + bv0.x, c0.y + bv0.y, c1.x + bv0.z, c1.y + bv0.w);
        float4 o1 = make_float4(c2.x + bv1.x, c2.y + bv1.y, c3.x + bv1.z, c3.y + bv1.w);
        float* yp = Y + (size_t)row * 512 + bn + tn;
        *(float4*)yp       = o0;
        *(float4*)(yp + 4) = o1;
    }
}

// ============================================================================
// Cluster-2 LSTM scan.  grid.x = 2*BATCH, cluster (2,1,1).
// ============================================================================
__global__ __launch_bounds__(512, 1) __cluster_dims__(2, 1, 1)
void lstm_scan(const float* __restrict__ xz, const float* __restrict__ U,
               float* __restrict__ hout, int T) {
    __shared__ __align__(16) float s_h[2][HID];
    __shared__ __align__(8)  ull   s_mb[4];   // full0, full1, empty0, empty1

    const int tid  = threadIdx.x;
    const int lane = tid & 31;
    const int rank = blockIdx.x & 1;
    const int b    = blockIdx.x >> 1;

    const int half = tid & 1;              // k half: 0 -> k 0..63, 1 -> k 64..127
    const int gate = (tid >> 1) & 3;       // i, f, g, o
    const int jj   = tid >> 3;             // 0..63
    const int j    = (rank << 6) + jj;     // global h column 0..127
    const int ucol = (gate << 7) + j;
    const int kb   = half << 6;

    // ---- one-time U load: 64 values fully in registers ----------------------
    ull ureg[32];
    #pragma unroll
    for (int q = 0; q < 32; ++q) {
        float u0 = U[(size_t)(kb + 2 * q)     * 512 + ucol];
        float u1 = U[(size_t)(kb + 2 * q + 1) * 512 + ucol];
        ureg[q] = pack2(u0, u1);
    }

    if (tid < HID) s_h[0][tid] = 0.0f;
    if (tid == 0) {
        mbar_init(smem_u32(&s_mb[0]), 128);  // full0: 64 local + 64 peer
        mbar_init(smem_u32(&s_mb[1]), 128);  // full1
        mbar_init(smem_u32(&s_mb[2]), 64);   // empty0: 64 peer arrivals
        mbar_init(smem_u32(&s_mb[3]), 64);   // empty1
    }
    __syncthreads();
    CLUSTER_SYNC_();                          // mbars + s_h[0] ready cluster-wide

    const uint32_t mb_l = smem_u32(&s_mb[0]);
    const uint32_t sh_l = smem_u32(&s_h[0][0]);
    const uint32_t rmb  = mapa_u32(mb_l, rank ^ 1);
    const uint32_t rsh  = mapa_u32(sh_l, rank ^ 1);

    const bool combiner = ((lane & 7) == 0);  // gate==0 && half==0
    if (combiner) {
        mbar_arrive_local(mb_l + 0);          // pre-seed full[0] (local h0=0 ready)
        mbar_arrive_remote(rmb + 0);          //    ... and peer's full[0]
        mbar_arrive_remote(rmb + 24);         // pre-seed peer's empty[1]
    }

    const float* xzp = xz + (size_t)b * T * 512 + ucol;
    float* hp = hout + (size_t)b * T * HID + j;
    float xz0 = __ldcs(xzp);
    float xz1 = __ldcs(xzp + 512);

    float c = 0.0f;
    const int lb = lane & 24;                 // shuffle base (j-group within warp)

    for (int t = 0; t < T; ++t) {
        const int ib  = t & 1;
        const int nb  = ib ^ 1;
        const int par = (t >> 1) & 1;

        MBAR_WAIT(mb_l + ib * 8, par);        // h(t) complete (local + peer)

        // dot over this thread's k-half
        const float* hh = &s_h[ib][kb];
        ull a0 = 0, a1 = 0, a2 = 0, a3 = 0;
        #pragma unroll
        for (int q = 0; q < 8; ++q) {
            double2 d0 = *(const double2*)(hh + 8 * q);
            double2 d1 = *(const double2*)(hh + 8 * q + 4);
            fma2(a0, d2u(d0.x), ureg[4 * q]);
            fma2(a1, d2u(d0.y), ureg[4 * q + 1]);
            fma2(a2, d2u(d1.x), ureg[4 * q + 2]);
            fma2(a3, d2u(d1.y), ureg[4 * q + 3]);
        }
        float2 f0 = unpack2(a0), f1 = unpack2(a1);
        float2 f2 = unpack2(a2), f3 = unpack2(a3);
        float part = ((f0.x + f0.y) + (f1.x + f1.y)) + ((f2.x + f2.y) + (f3.x + f3.y));
        float z = xz0 + part + __shfl_xor_sync(0xffffffffu, part, 1);

        // rotate xz prefetch (depth 2)
        xz0 = xz1;
        int tp = (t + 2 < T) ? t + 2 : t;
        xz1 = __ldcs(xzp + (size_t)tp * 512);

        // activation (both k-halves compute identically; no divergence)
        float e   = __expf(gate == 2 ? z : -z);
        float sig = __fdividef(1.0f, 1.0f + e);
        float act = (gate == 2)
                  ? ((z > 0.0f) ? SELU_LAM * z : (SELU_LAM * SELU_ALF) * (e - 1.0f))
                  : sig;

        float af = __shfl_sync(0xffffffffu, act, lb | 2);
        float ag = __shfl_sync(0xffffffffu, act, lb | 4);
        float ao = __shfl_sync(0xffffffffu, act, lb | 6);

        __syncthreads();                       // all reads of s_h[ib] done CTA-wide

        if (combiner) {
            mbar_arrive_remote(rmb + 16 + ib * 8);   // release buf ib to peer
            MBAR_WAIT(mb_l + 16 + nb * 8, par);      // peer done reading buf nb

            c = af * c + act * ag;
            float sc = (c > 0.0f) ? SELU_LAM * c
                                  : (SELU_LAM * SELU_ALF) * (__expf(c) - 1.0f);
            float h = ao * sc;

            s_h[nb][j] = h;
            mbar_arrive_local(mb_l + nb * 8);        // local h published
            st_remote_f32(rsh + (uint32_t)(nb * HID + j) * 4, h);
            mbar_arrive_remote(rmb + nb * 8);        // peer h published (release)

            hp[(size_t)t * HID] = h;
        }
    }
    CLUSTER_SYNC_();   // keep cluster alive until all remote traffic consumed
}

// ============================================================================
// kernel_launch — inputs: x, W1, U1, b1, W2, U2, b2 (fp32); out: [B,T,H] fp32.
// ============================================================================
extern "C" void kernel_launch(void* const* d_in, const int* in_sizes, int n_in,
                              void* d_out, int out_size) {
    (void)in_sizes; (void)n_in; (void)out_size;
    const float* x  = (const float*)d_in[0];
    const float* W1 = (const float*)d_in[1];
    const float* U1 = (const float*)d_in[2];
    const float* b1 = (const float*)d_in[3];
    const float* W2 = (const float*)d_in[4];
    const float* U2 = (const float*)d_in[5];
    const float* b2 = (const float*)d_in[6];
    float* out = (float*)d_out;

    void *pxz = nullptr, *ph1 = nullptr;
    cudaGetSymbolAddress(&pxz, g_xz);
    cudaGetSymbolAddress(&ph1, g_h1);
    float* xz = (float*)pxz;
    float* h1 = (float*)ph1;

    const int smemA = (128 * (FIN + 1) + FIN * 128) * 4;    //  66048 B
    const int smemB = (128 * (HID + 1) + HID * 128) * 4;    // 131584 B
    cudaFuncSetAttribute(gemm_xz<FIN>, cudaFuncAttributeMaxDynamicSharedMemorySize, smemA);
    cudaFuncSetAttribute(gemm_xz<HID>, cudaFuncAttributeMaxDynamicSharedMemorySize, smemB);

    dim3 gg((BATCH * TSEQ) / 128, 4);

    gemm_xz<FIN><<<gg, 256, smemA>>>(x, W1, b1, xz);
    lstm_scan<<<2 * BATCH, 512>>>(xz, U1, h1, TSEQ);
    gemm_xz<HID><<<gg, 256, smemB>>>(h1, W2, b2, xz);
    lstm_scan<<<2 * BATCH, 512>>>(xz, U2, out, TSEQ);
}

// round 9
// speedup vs baseline: 1.0009x; 1.0009x over previous
#include <cuda_runtime.h>
#include <cstdint>
#include <cstddef>

// ============================================================================
// RNNLayers: 2-layer LSTM (Keras, activation=selu), B=64, T=2048, F=64, H=128.
//   1) GEMM1: xz = x  @ W1 + b1   -> g_xz   [131072 x 512]
//   2) scan1 (cluster-2): LSTM    -> g_h1
//   3) GEMM2: xz = h1 @ W2 + b2   -> g_xz
//   4) scan2 (cluster-2): LSTM    -> d_out
//
// Scan: each batch row is split across a 2-CTA cluster. CTA rank r owns
// gate-columns ucol = gate*128 + j, j in [r*64, r*64+64). 512 threads:
// bit0 = k-half, bits1-2 = gate, bits3-8 = jj. U is FULLY register-resident
// (64 floats = 32 f32x2 per thread). h (128 floats) is replicated in each
// CTA's smem; per step each CTA writes its 64 new h values locally and to the
// peer via st.shared::cluster, synchronized with full/empty mbarriers.
// ============================================================================

typedef unsigned long long ull;

#define BATCH 64
#define TSEQ  2048
#define FIN   64
#define HID   128

#define SELU_LAM 1.0507009873554804934193349852946f
#define SELU_ALF 1.6732632423543772848170429916717f

__device__ float g_xz[(size_t)BATCH * TSEQ * 4 * HID];  // 256 MB scratch
__device__ float g_h1[(size_t)BATCH * TSEQ * HID];      //  64 MB scratch

__device__ __forceinline__ void fma2(ull& d, ull a, ull b) {
    asm("fma.rn.f32x2 %0, %1, %2, %0;" : "+l"(d) : "l"(a), "l"(b));
}
__device__ __forceinline__ ull pack2(float lo, float hi) {
    ull r; asm("mov.b64 %0, {%1, %2};" : "=l"(r) : "f"(lo), "f"(hi)); return r;
}
__device__ __forceinline__ float2 unpack2(ull v) {
    float2 r; asm("mov.b64 {%0, %1}, %2;" : "=f"(r.x), "=f"(r.y) : "l"(v)); return r;
}
__device__ __forceinline__ ull d2u(double d) { return (ull)__double_as_longlong(d); }

__device__ __forceinline__ uint32_t smem_u32(const void* p) {
    return (uint32_t)__cvta_generic_to_shared(p);
}
__device__ __forceinline__ uint32_t mapa_u32(uint32_t addr, uint32_t rank) {
    uint32_t r; asm("mapa.shared::cluster.u32 %0, %1, %2;" : "=r"(r) : "r"(addr), "r"(rank));
    return r;
}
__device__ __forceinline__ void st_remote_f32(uint32_t raddr, float v) {
    asm volatile("st.shared::cluster.f32 [%0], %1;" :: "r"(raddr), "f"(v) : "memory");
}
__device__ __forceinline__ void mbar_init(uint32_t a, uint32_t cnt) {
    asm volatile("mbarrier.init.shared.b64 [%0], %1;" :: "r"(a), "r"(cnt) : "memory");
}
__device__ __forceinline__ void mbar_arrive_local(uint32_t a) {
    asm volatile("mbarrier.arrive.shared.b64 _, [%0];" :: "r"(a) : "memory");
}
__device__ __forceinline__ void mbar_arrive_remote(uint32_t raddr) {
    asm volatile("mbarrier.arrive.release.cluster.shared::cluster.b64 _, [%0];"
                 :: "r"(raddr) : "memory");
}
#define MBAR_WAIT(addr, par) do {                                              \
    uint32_t _done;                                                            \
    asm volatile("{\n\t.reg .pred p;\n\t"                                      \
        "mbarrier.try_wait.parity.acquire.cluster.shared::cta.b64 p, [%1], %2;\n\t" \
        "selp.b32 %0, 1, 0, p;\n\t}"                                           \
        : "=r"(_done) : "r"(addr), "r"(par) : "memory");                       \
    while (!_done) {                                                           \
        asm volatile("{\n\t.reg .pred p;\n\t"                                  \
            "mbarrier.try_wait.parity.acquire.cluster.shared::cta.b64 p, [%1], %2, 0x989680;\n\t" \
            "selp.b32 %0, 1, 0, p;\n\t}"                                       \
            : "=r"(_done) : "r"(addr), "r"(par) : "memory");                   \
    }                                                                          \
} while (0)
#define CLUSTER_SYNC_() do {                                                   \
    asm volatile("barrier.cluster.arrive.aligned;" ::: "memory");              \
    asm volatile("barrier.cluster.wait.aligned;" ::: "memory");                \
} while (0)

// ============================================================================
// GEMM: Y[M,512] = X[M,K] @ W[K,512] + bias.  BM=128, BN=128, K loaded whole.
// ============================================================================
template<int K>
__global__ __launch_bounds__(256, 1)
void gemm_xz(const float* __restrict__ X, const float* __restrict__ W,
             const float* __restrict__ bias, float* __restrict__ Y) {
    extern __shared__ float sm[];
    float* s_a = sm;                     // [128][K+1]
    float* s_b = sm + 128 * (K + 1);     // [K][128]
    const int tid = threadIdx.x;
    const int bm  = blockIdx.x * 128;
    const int bn  = blockIdx.y * 128;

    #pragma unroll 8
    for (int i = tid; i < 128 * K; i += 256) {
        int m = i / K, k = i - m * K;
        s_a[m * (K + 1) + k] = X[(size_t)(bm + m) * K + k];
    }
    #pragma unroll 4
    for (int i = tid * 4; i < K * 128; i += 1024) {
        int k = i >> 7, n = i & 127;
        *(float4*)(s_b + k * 128 + n) = *(const float4*)(W + (size_t)k * 512 + bn + n);
    }
    __syncthreads();

    const int tmi = tid & 15;
    const int tn  = (tid >> 4) << 3;
    ull acc[8][4] = {};
    const float* sbp = s_b + tn;

    #pragma unroll 4
    for (int k = 0; k < K; ++k) {
        float4 b0 = *(const float4*)(sbp + k * 128);
        float4 b1 = *(const float4*)(sbp + k * 128 + 4);
        ull bb0 = pack2(b0.x, b0.y), bb1 = pack2(b0.z, b0.w);
        ull bb2 = pack2(b1.x, b1.y), bb3 = pack2(b1.z, b1.w);
        #pragma unroll
        for (int r = 0; r < 8; ++r) {
            float a = s_a[(tmi + (r << 4)) * (K + 1) + k];
            ull aa = pack2(a, a);
            fma2(acc[r][0], aa, bb0);
            fma2(acc[r][1], aa, bb1);
            fma2(acc[r][2], aa, bb2);
            fma2(acc[r][3], aa, bb3);
        }
    }

    float4 bv0 = *(const float4*)(bias + bn + tn);
    float4 bv1 = *(const float4*)(bias + bn + tn + 4);
    #pragma unroll
    for (int r = 0; r < 8; ++r) {
        int row = bm + tmi + (r << 4);
        float2 c0 = unpack2(acc[r][0]);
        float2 c1 = unpack2(acc[r][1]);
        float2 c2 = unpack2(acc[r][2]);
        float2 c3 = unpack2(acc[r][3]);
        float4 o0 = make_float4(c0.x + bv0.x, c0.y + bv0.y, c1.x + bv0.z, c1.y + bv0.w);
        float4 o1 = make_float4(c2.x + bv1.x, c2.y + bv1.y, c3.x + bv1.z, c3.y + bv1.w);
        float* yp = Y + (size_t)row * 512 + bn + tn;
        *(float4*)yp       = o0;
        *(float4*)(yp + 4) = o1;
    }
}

// ============================================================================
// Cluster-2 LSTM scan.  grid.x = 2*BATCH, cluster (2,1,1).
// ============================================================================
__global__ __launch_bounds__(512, 1) __cluster_dims__(2, 1, 1)
void lstm_scan(const float* __restrict__ xz, const float* __restrict__ U,
               float* __restrict__ hout, int T) {
    __shared__ __align__(16) float s_h[2][HID];
    __shared__ __align__(8)  ull   s_mb[4];   // full0, full1, empty0, empty1

    const int tid  = threadIdx.x;
    const int lane = tid & 31;
    const int rank = blockIdx.x & 1;
    const int b    = blockIdx.x >> 1;

    const int half = tid & 1;              // k half: 0 -> k 0..63, 1 -> k 64..127
    const int gate = (tid >> 1) & 3;       // i, f, g, o
    const int jj   = tid >> 3;             // 0..63
    const int j    = (rank << 6) + jj;     // global h column 0..127
    const int ucol = (gate << 7) + j;
    const int kb   = half << 6;

    // ---- one-time U load: 64 values fully in registers ----------------------
    ull ureg[32];
    #pragma unroll
    for (int q = 0; q < 32; ++q) {
        float u0 = U[(size_t)(kb + 2 * q)     * 512 + ucol];
        float u1 = U[(size_t)(kb + 2 * q + 1) * 512 + ucol];
        ureg[q] = pack2(u0, u1);
    }

    if (tid < HID) s_h[0][tid] = 0.0f;
    if (tid == 0) {
        mbar_init(smem_u32(&s_mb[0]), 128);  // full0: 64 local + 64 peer
        mbar_init(smem_u32(&s_mb[1]), 128);  // full1
        mbar_init(smem_u32(&s_mb[2]), 64);   // empty0: 64 peer arrivals
        mbar_init(smem_u32(&s_mb[3]), 64);   // empty1
    }
    __syncthreads();
    CLUSTER_SYNC_();                          // mbars + s_h[0] ready cluster-wide

    const uint32_t mb_l = smem_u32(&s_mb[0]);
    const uint32_t sh_l = smem_u32(&s_h[0][0]);
    const uint32_t rmb  = mapa_u32(mb_l, rank ^ 1);
    const uint32_t rsh  = mapa_u32(sh_l, rank ^ 1);

    const bool combiner = ((lane & 7) == 0);  // gate==0 && half==0
    if (combiner) {
        mbar_arrive_local(mb_l + 0);          // pre-seed full[0] (local h0=0 ready)
        mbar_arrive_remote(rmb + 0);          //    ... and peer's full[0]
        mbar_arrive_remote(rmb + 24);         // pre-seed peer's empty[1]
    }

    const float* xzp = xz + (size_t)b * T * 512 + ucol;
    float* hp = hout + (size_t)b * T * HID + j;
    float xz0 = __ldcs(xzp);
    float xz1 = __ldcs(xzp + 512);

    float c = 0.0f;
    const int lb = lane & 24;                 // shuffle base (j-group within warp)

    for (int t = 0; t < T; ++t) {
        const int ib  = t & 1;
        const int nb  = ib ^ 1;
        const int par = (t >> 1) & 1;

        MBAR_WAIT(mb_l + ib * 8, par);        // h(t) complete (local + peer)

        // dot over this thread's k-half
        const float* hh = &s_h[ib][kb];
        ull a0 = 0, a1 = 0, a2 = 0, a3 = 0;
        #pragma unroll
        for (int q = 0; q < 8; ++q) {
            double2 d0 = *(const double2*)(hh + 8 * q);
            double2 d1 = *(const double2*)(hh + 8 * q + 4);
            fma2(a0, d2u(d0.x), ureg[4 * q]);
            fma2(a1, d2u(d0.y), ureg[4 * q + 1]);
            fma2(a2, d2u(d1.x), ureg[4 * q + 2]);
            fma2(a3, d2u(d1.y), ureg[4 * q + 3]);
        }
        float2 f0 = unpack2(a0), f1 = unpack2(a1);
        float2 f2 = unpack2(a2), f3 = unpack2(a3);
        float part = ((f0.x + f0.y) + (f1.x + f1.y)) + ((f2.x + f2.y) + (f3.x + f3.y));
        float z = xz0 + part + __shfl_xor_sync(0xffffffffu, part, 1);

        // rotate xz prefetch (depth 2)
        xz0 = xz1;
        int tp = (t + 2 < T) ? t + 2 : t;
        xz1 = __ldcs(xzp + (size_t)tp * 512);

        // activation (both k-halves compute identically; no divergence)
        float e   = __expf(gate == 2 ? z : -z);
        float sig = __fdividef(1.0f, 1.0f + e);
        float act = (gate == 2)
                  ? ((z > 0.0f) ? SELU_LAM * z : (SELU_LAM * SELU_ALF) * (e - 1.0f))
                  : sig;

        float af = __shfl_sync(0xffffffffu, act, lb | 2);
        float ag = __shfl_sync(0xffffffffu, act, lb | 4);
        float ao = __shfl_sync(0xffffffffu, act, lb | 6);

        __syncthreads();                       // all reads of s_h[ib] done CTA-wide

        if (combiner) {
            mbar_arrive_remote(rmb + 16 + ib * 8);   // release buf ib to peer
            MBAR_WAIT(mb_l + 16 + nb * 8, par);      // peer done reading buf nb

            c = af * c + act * ag;
            float sc = (c > 0.0f) ? SELU_LAM * c
                                  : (SELU_LAM * SELU_ALF) * (__expf(c) - 1.0f);
            float h = ao * sc;

            s_h[nb][j] = h;
            mbar_arrive_local(mb_l + nb * 8);        // local h published
            st_remote_f32(rsh + (uint32_t)(nb * HID + j) * 4, h);
            mbar_arrive_remote(rmb + nb * 8);        // peer h published (release)

            hp[(size_t)t * HID] = h;
        }
    }
    CLUSTER_SYNC_();   // keep cluster alive until all remote traffic consumed
}

// ============================================================================
// kernel_launch — inputs: x, W1, U1, b1, W2, U2, b2 (fp32); out: [B,T,H] fp32.
// ============================================================================
extern "C" void kernel_launch(void* const* d_in, const int* in_sizes, int n_in,
                              void* d_out, int out_size) {
    (void)in_sizes; (void)n_in; (void)out_size;
    const float* x  = (const float*)d_in[0];
    const float* W1 = (const float*)d_in[1];
    const float* U1 = (const float*)d_in[2];
    const float* b1 = (const float*)d_in[3];
    const float* W2 = (const float*)d_in[4];
    const float* U2 = (const float*)d_in[5];
    const float* b2 = (const float*)d_in[6];
    float* out = (float*)d_out;

    void *pxz = nullptr, *ph1 = nullptr;
    cudaGetSymbolAddress(&pxz, g_xz);
    cudaGetSymbolAddress(&ph1, g_h1);
    float* xz = (float*)pxz;
    float* h1 = (float*)ph1;

    const int smemA = (128 * (FIN + 1) + FIN * 128) * 4;    //  66048 B
    const int smemB = (128 * (HID + 1) + HID * 128) * 4;    // 131584 B
    cudaFuncSetAttribute(gemm_xz<FIN>, cudaFuncAttributeMaxDynamicSharedMemorySize, smemA);
    cudaFuncSetAttribute(gemm_xz<HID>, cudaFuncAttributeMaxDynamicSharedMemorySize, smemB);

    dim3 gg((BATCH * TSEQ) / 128, 4);

    gemm_xz<FIN><<<gg, 256, smemA>>>(x, W1, b1, xz);
    lstm_scan<<<2 * BATCH, 512>>>(xz, U1, h1, TSEQ);
    gemm_xz<HID><<<gg, 256, smemB>>>(h1, W2, b2, xz);
    lstm_scan<<<2 * BATCH, 512>>>(xz, U2, out, TSEQ);
}

// round 10
// speedup vs baseline: 1.0029x; 1.0020x over previous
#include <cuda_runtime.h>
#include <cstdint>
#include <cstddef>

// ============================================================================
// RNNLayers: 2-layer LSTM (Keras, activation=selu), B=64, T=2048, F=64, H=128.
//   1) GEMM1: xz = x  @ W1 + b1   -> g_xz   [131072 x 512]
//   2) scan1 (cluster-2): LSTM    -> g_h1
//   3) GEMM2: xz = h1 @ W2 + b2   -> g_xz
//   4) scan2 (cluster-2): LSTM    -> d_out
//
// Scan: each batch row is split across a 2-CTA cluster. CTA rank r owns
// gate-columns ucol = gate*128 + j, j in [r*64, r*64+64). 512 threads:
// bit0 = k-half, bits1-2 = gate, bits3-8 = jj. U is FULLY register-resident
// (64 floats = 32 f32x2 per thread). h (128 floats) is replicated in each
// CTA's smem; per step each CTA writes its 64 new h values locally and to the
// peer via st.shared::cluster, synchronized with full/empty mbarriers.
// ============================================================================

typedef unsigned long long ull;

#define BATCH 64
#define TSEQ  2048
#define FIN   64
#define HID   128

#define SELU_LAM 1.0507009873554804934193349852946f
#define SELU_ALF 1.6732632423543772848170429916717f

__device__ float g_xz[(size_t)BATCH * TSEQ * 4 * HID];  // 256 MB scratch
__device__ float g_h1[(size_t)BATCH * TSEQ * HID];      //  64 MB scratch

__device__ __forceinline__ void fma2(ull& d, ull a, ull b) {
    asm("fma.rn.f32x2 %0, %1, %2, %0;" : "+l"(d) : "l"(a), "l"(b));
}
__device__ __forceinline__ ull pack2(float lo, float hi) {
    ull r; asm("mov.b64 %0, {%1, %2};" : "=l"(r) : "f"(lo), "f"(hi)); return r;
}
__device__ __forceinline__ float2 unpack2(ull v) {
    float2 r; asm("mov.b64 {%0, %1}, %2;" : "=f"(r.x), "=f"(r.y) : "l"(v)); return r;
}
__device__ __forceinline__ ull d2u(double d) { return (ull)__double_as_longlong(d); }

__device__ __forceinline__ uint32_t smem_u32(const void* p) {
    return (uint32_t)__cvta_generic_to_shared(p);
}
__device__ __forceinline__ uint32_t mapa_u32(uint32_t addr, uint32_t rank) {
    uint32_t r; asm("mapa.shared::cluster.u32 %0, %1, %2;" : "=r"(r) : "r"(addr), "r"(rank));
    return r;
}
__device__ __forceinline__ void st_remote_f32(uint32_t raddr, float v) {
    asm volatile("st.shared::cluster.f32 [%0], %1;" :: "r"(raddr), "f"(v) : "memory");
}
__device__ __forceinline__ void mbar_init(uint32_t a, uint32_t cnt) {
    asm volatile("mbarrier.init.shared.b64 [%0], %1;" :: "r"(a), "r"(cnt) : "memory");
}
__device__ __forceinline__ void mbar_arrive_local(uint32_t a) {
    asm volatile("mbarrier.arrive.shared.b64 _, [%0];" :: "r"(a) : "memory");
}
__device__ __forceinline__ void mbar_arrive_remote(uint32_t raddr) {
    asm volatile("mbarrier.arrive.release.cluster.shared::cluster.b64 _, [%0];"
                 :: "r"(raddr) : "memory");
}
#define MBAR_WAIT(addr, par) do {                                              \
    uint32_t _done;                                                            \
    asm volatile("{\n\t.reg .pred p;\n\t"                                      \
        "mbarrier.try_wait.parity.acquire.cluster.shared::cta.b64 p, [%1], %2;\n\t" \
        "selp.b32 %0, 1, 0, p;\n\t}"                                           \
        : "=r"(_done) : "r"(addr), "r"(par) : "memory");                       \
    while (!_done) {                                                           \
        asm volatile("{\n\t.reg .pred p;\n\t"                                  \
            "mbarrier.try_wait.parity.acquire.cluster.shared::cta.b64 p, [%1], %2, 0x989680;\n\t" \
            "selp.b32 %0, 1, 0, p;\n\t}"                                       \
            : "=r"(_done) : "r"(addr), "r"(par) : "memory");                   \
    }                                                                          \
} while (0)
#define CLUSTER_SYNC_() do {                                                   \
    asm volatile("barrier.cluster.arrive.aligned;" ::: "memory");              \
    asm volatile("barrier.cluster.wait.aligned;" ::: "memory");                \
} while (0)

// ============================================================================
// GEMM: Y[M,512] = X[M,K] @ W[K,512] + bias.  BM=128, BN=128, K loaded whole.
// ============================================================================
template<int K>
__global__ __launch_bounds__(256, 1)
void gemm_xz(const float* __restrict__ X, const float* __restrict__ W,
             const float* __restrict__ bias, float* __restrict__ Y) {
    extern __shared__ float sm[];
    float* s_a = sm;                     // [128][K+1]
    float* s_b = sm + 128 * (K + 1);     // [K][128]
    const int tid = threadIdx.x;
    const int bm  = blockIdx.x * 128;
    const int bn  = blockIdx.y * 128;

    #pragma unroll 8
    for (int i = tid; i < 128 * K; i += 256) {
        int m = i / K, k = i - m * K;
        s_a[m * (K + 1) + k] = X[(size_t)(bm + m) * K + k];
    }
    #pragma unroll 4
    for (int i = tid * 4; i < K * 128; i += 1024) {
        int k = i >> 7, n = i & 127;
        *(float4*)(s_b + k * 128 + n) = *(const float4*)(W + (size_t)k * 512 + bn + n);
    }
    __syncthreads();

    const int tmi = tid & 15;
    const int tn  = (tid >> 4) << 3;
    ull acc[8][4] = {};
    const float* sbp = s_b + tn;

    #pragma unroll 4
    for (int k = 0; k < K; ++k) {
        float4 b0 = *(const float4*)(sbp + k * 128);
        float4 b1 = *(const float4*)(sbp + k * 128 + 4);
        ull bb0 = pack2(b0.x, b0.y), bb1 = pack2(b0.z, b0.w);
        ull bb2 = pack2(b1.x, b1.y), bb3 = pack2(b1.z, b1.w);
        #pragma unroll
        for (int r = 0; r < 8; ++r) {
            float a = s_a[(tmi + (r << 4)) * (K + 1) + k];
            ull aa = pack2(a, a);
            fma2(acc[r][0], aa, bb0);
            fma2(acc[r][1], aa, bb1);
            fma2(acc[r][2], aa, bb2);
            fma2(acc[r][3], aa, bb3);
        }
    }

    float4 bv0 = *(const float4*)(bias + bn + tn);
    float4 bv1 = *(const float4*)(bias + bn + tn + 4);
    #pragma unroll
    for (int r = 0; r < 8; ++r) {
        int row = bm + tmi + (r << 4);
        float2 c0 = unpack2(acc[r][0]);
        float2 c1 = unpack2(acc[r][1]);
        float2 c2 = unpack2(acc[r][2]);
        float2 c3 = unpack2(acc[r][3]);
        float4 o0 = make_float4(c0.x + bv0.x, c0.y + bv0.y, c1.x + bv0.z, c1.y + bv0.w);
        float4 o1 = make_float4(c2.x + bv1.x, c2.y + bv1.y, c3.x + bv1.z, c3.y + bv1.w);
        float* yp = Y + (size_t)row * 512 + bn + tn;
        *(float4*)yp       = o0;
        *(float4*)(yp + 4) = o1;
    }
}

// ============================================================================
// Cluster-2 LSTM scan.  grid.x = 2*BATCH, cluster (2,1,1).
// ============================================================================
__global__ __launch_bounds__(512, 1) __cluster_dims__(2, 1, 1)
void lstm_scan(const float* __restrict__ xz, const float* __restrict__ U,
               float* __restrict__ hout, int T) {
    __shared__ __align__(16) float s_h[2][HID];
    __shared__ __align__(8)  ull   s_mb[4];   // full0, full1, empty0, empty1

    const int tid  = threadIdx.x;
    const int lane = tid & 31;
    const int rank = blockIdx.x & 1;
    const int b    = blockIdx.x >> 1;

    const int half = tid & 1;              // k half: 0 -> k 0..63, 1 -> k 64..127
    const int gate = (tid >> 1) & 3;       // i, f, g, o
    const int jj   = tid >> 3;             // 0..63
    const int j    = (rank << 6) + jj;     // global h column 0..127
    const int ucol = (gate << 7) + j;
    const int kb   = half << 6;

    // ---- one-time U load: 64 values fully in registers ----------------------
    ull ureg[32];
    #pragma unroll
    for (int q = 0; q < 32; ++q) {
        float u0 = U[(size_t)(kb + 2 * q)     * 512 + ucol];
        float u1 = U[(size_t)(kb + 2 * q + 1) * 512 + ucol];
        ureg[q] = pack2(u0, u1);
    }

    if (tid < HID) s_h[0][tid] = 0.0f;
    if (tid == 0) {
        mbar_init(smem_u32(&s_mb[0]), 128);  // full0: 64 local + 64 peer
        mbar_init(smem_u32(&s_mb[1]), 128);  // full1
        mbar_init(smem_u32(&s_mb[2]), 64);   // empty0: 64 peer arrivals
        mbar_init(smem_u32(&s_mb[3]), 64);   // empty1
    }
    __syncthreads();
    CLUSTER_SYNC_();                          // mbars + s_h[0] ready cluster-wide

    const uint32_t mb_l = smem_u32(&s_mb[0]);
    const uint32_t sh_l = smem_u32(&s_h[0][0]);
    const uint32_t rmb  = mapa_u32(mb_l, rank ^ 1);
    const uint32_t rsh  = mapa_u32(sh_l, rank ^ 1);

    const bool combiner = ((lane & 7) == 0);  // gate==0 && half==0
    if (combiner) {
        mbar_arrive_local(mb_l + 0);          // pre-seed full[0] (local h0=0 ready)
        mbar_arrive_remote(rmb + 0);          //    ... and peer's full[0]
        mbar_arrive_remote(rmb + 24);         // pre-seed peer's empty[1]
    }

    const float* xzp = xz + (size_t)b * T * 512 + ucol;
    float* hp = hout + (size_t)b * T * HID + j;
    float xz0 = __ldcs(xzp);
    float xz1 = __ldcs(xzp + 512);

    float c = 0.0f;
    const int lb = lane & 24;                 // shuffle base (j-group within warp)

    for (int t = 0; t < T; ++t) {
        const int ib  = t & 1;
        const int nb  = ib ^ 1;
        const int par = (t >> 1) & 1;

        MBAR_WAIT(mb_l + ib * 8, par);        // h(t) complete (local + peer)

        // dot over this thread's k-half
        const float* hh = &s_h[ib][kb];
        ull a0 = 0, a1 = 0, a2 = 0, a3 = 0;
        #pragma unroll
        for (int q = 0; q < 8; ++q) {
            double2 d0 = *(const double2*)(hh + 8 * q);
            double2 d1 = *(const double2*)(hh + 8 * q + 4);
            fma2(a0, d2u(d0.x), ureg[4 * q]);
            fma2(a1, d2u(d0.y), ureg[4 * q + 1]);
            fma2(a2, d2u(d1.x), ureg[4 * q + 2]);
            fma2(a3, d2u(d1.y), ureg[4 * q + 3]);
        }
        float2 f0 = unpack2(a0), f1 = unpack2(a1);
        float2 f2 = unpack2(a2), f3 = unpack2(a3);
        float part = ((f0.x + f0.y) + (f1.x + f1.y)) + ((f2.x + f2.y) + (f3.x + f3.y));
        float z = xz0 + part + __shfl_xor_sync(0xffffffffu, part, 1);

        // rotate xz prefetch (depth 2)
        xz0 = xz1;
        int tp = (t + 2 < T) ? t + 2 : t;
        xz1 = __ldcs(xzp + (size_t)tp * 512);

        // activation (both k-halves compute identically; no divergence)
        float e   = __expf(gate == 2 ? z : -z);
        float sig = __fdividef(1.0f, 1.0f + e);
        float act = (gate == 2)
                  ? ((z > 0.0f) ? SELU_LAM * z : (SELU_LAM * SELU_ALF) * (e - 1.0f))
                  : sig;

        float af = __shfl_sync(0xffffffffu, act, lb | 2);
        float ag = __shfl_sync(0xffffffffu, act, lb | 4);
        float ao = __shfl_sync(0xffffffffu, act, lb | 6);

        __syncthreads();                       // all reads of s_h[ib] done CTA-wide

        if (combiner) {
            mbar_arrive_remote(rmb + 16 + ib * 8);   // release buf ib to peer
            MBAR_WAIT(mb_l + 16 + nb * 8, par);      // peer done reading buf nb

            c = af * c + act * ag;
            float sc = (c > 0.0f) ? SELU_LAM * c
                                  : (SELU_LAM * SELU_ALF) * (__expf(c) - 1.0f);
            float h = ao * sc;

            s_h[nb][j] = h;
            mbar_arrive_local(mb_l + nb * 8);        // local h published
            st_remote_f32(rsh + (uint32_t)(nb * HID + j) * 4, h);
            mbar_arrive_remote(rmb + nb * 8);        // peer h published (release)

            hp[(size_t)t * HID] = h;
        }
    }
    CLUSTER_SYNC_();   // keep cluster alive until all remote traffic consumed
}

// ============================================================================
// kernel_launch — inputs: x, W1, U1, b1, W2, U2, b2 (fp32); out: [B,T,H] fp32.
// ============================================================================
extern "C" void kernel_launch(void* const* d_in, const int* in_sizes, int n_in,
                              void* d_out, int out_size) {
    (void)in_sizes; (void)n_in; (void)out_size;
    const float* x  = (const float*)d_in[0];
    const float* W1 = (const float*)d_in[1];
    const float* U1 = (const float*)d_in[2];
    const float* b1 = (const float*)d_in[3];
    const float* W2 = (const float*)d_in[4];
    const float* U2 = (const float*)d_in[5];
    const float* b2 = (const float*)d_in[6];
    float* out = (float*)d_out;

    void *pxz = nullptr, *ph1 = nullptr;
    cudaGetSymbolAddress(&pxz, g_xz);
    cudaGetSymbolAddress(&ph1, g_h1);
    float* xz = (float*)pxz;
    float* h1 = (float*)ph1;

    const int smemA = (128 * (FIN + 1) + FIN * 128) * 4;    //  66048 B
    const int smemB = (128 * (HID + 1) + HID * 128) * 4;    // 131584 B
    cudaFuncSetAttribute(gemm_xz<FIN>, cudaFuncAttributeMaxDynamicSharedMemorySize, smemA);
    cudaFuncSetAttribute(gemm_xz<HID>, cudaFuncAttributeMaxDynamicSharedMemorySize, smemB);

    dim3 gg((BATCH * TSEQ) / 128, 4);

    gemm_xz<FIN><<<gg, 256, smemA>>>(x, W1, b1, xz);
    lstm_scan<<<2 * BATCH, 512>>>(xz, U1, h1, TSEQ);
    gemm_xz<HID><<<gg, 256, smemB>>>(h1, W2, b2, xz);
    lstm_scan<<<2 * BATCH, 512>>>(xz, U2, out, TSEQ);
}